// round 1
// baseline (speedup 1.0000x reference)
#include <cuda_runtime.h>
#include <math.h>

// Problem-shape maxima (dataset is fixed: N_E=100000, N_R=1000, E=1e6, HID=128)
#define MAX_NE 100000
#define MAX_NR 1000
#define MAX_E  1000000

// ---------------- scratch (device globals; no allocation allowed) ----------------
__device__ float  g_sh[MAX_NE];            // x_e @ w_ah
__device__ float  g_st[MAX_NE];            // x_e @ w_at
__device__ float  g_sr[MAX_NR];            // x_r @ w_ar
__device__ float  g_hid[MAX_NR * 256];     // x_r @ W_r1 + b1
__device__ float  g_msg[MAX_NR * 128];     // x_r + (hid @ W_r2 + b2)
__device__ float  g_P[16 * MAX_NR * 32];   // [sidechunk(16)][rel][32]  (P_h chunks 0..7, P_t chunks 8..15)
__device__ int    g_cnt_h[MAX_NE];
__device__ int    g_cnt_t[MAX_NE];
__device__ int    g_starts_h[MAX_NE + 1];
__device__ int    g_starts_t[MAX_NE + 1];
__device__ int    g_cur_h[MAX_NE];
__device__ int    g_cur_t[MAX_NE];
__device__ float2 g_pack_h[MAX_E];         // sorted-by-h: {alpha (z then normalized), rel*32 as int bits}
__device__ float2 g_pack_t[MAX_E];         // sorted-by-t
__device__ int    g_bsum[2][160];          // scan block sums (h=0, t=1)

// ---------------- init ----------------
__global__ void k_zero(int n_e) {
    int i = blockIdx.x * blockDim.x + threadIdx.x;
    if (i < n_e) { g_cnt_h[i] = 0; g_cnt_t[i] = 0; }
}

// ---------------- per-node attention scores: warp per node, float4 lanes ----------------
__global__ void k_node_scores(const float4* __restrict__ xe,
                              const float4* __restrict__ wah4,
                              const float4* __restrict__ wat4, int n_e) {
    int gw = (blockIdx.x * blockDim.x + threadIdx.x) >> 5;
    int lane = threadIdx.x & 31;
    if (gw >= n_e) return;
    float4 v = xe[(size_t)gw * 32 + lane];
    float4 a = wah4[lane];
    float4 b = wat4[lane];
    float da = v.x * a.x + v.y * a.y + v.z * a.z + v.w * a.w;
    float db = v.x * b.x + v.y * b.y + v.z * b.z + v.w * b.w;
#pragma unroll
    for (int o = 16; o > 0; o >>= 1) {
        da += __shfl_xor_sync(0xffffffffu, da, o);
        db += __shfl_xor_sync(0xffffffffu, db, o);
    }
    if (lane == 0) { g_sh[gw] = da; g_st[gw] = db; }
}

__global__ void k_rel_scores(const float4* __restrict__ xr,
                             const float4* __restrict__ war4, int n_r) {
    int gw = (blockIdx.x * blockDim.x + threadIdx.x) >> 5;
    int lane = threadIdx.x & 31;
    if (gw >= n_r) return;
    float4 v = xr[gw * 32 + lane];
    float4 a = war4[lane];
    float d = v.x * a.x + v.y * a.y + v.z * a.z + v.w * a.w;
#pragma unroll
    for (int o = 16; o > 0; o >>= 1) d += __shfl_xor_sync(0xffffffffu, d, o);
    if (lane == 0) g_sr[gw] = d;
}

// ---------------- relation MLP: hid = x_r @ W1 + b1 ----------------
__global__ void k_hid(const float* __restrict__ xr, const float* __restrict__ W1,
                      const float* __restrict__ b1, int n_r) {
    __shared__ float sx[512];  // 4 relation rows x 128
    int r0 = blockIdx.x * 4;
    for (int i = threadIdx.x; i < 512; i += 256) {
        int rr = i >> 7, k = i & 127, r = r0 + rr;
        sx[i] = (r < n_r) ? xr[r * 128 + k] : 0.f;
    }
    __syncthreads();
    int j = threadIdx.x;
    float a0 = 0, a1 = 0, a2 = 0, a3 = 0;
#pragma unroll 4
    for (int k = 0; k < 128; k++) {
        float w = W1[k * 256 + j];
        a0 += sx[k] * w; a1 += sx[128 + k] * w; a2 += sx[256 + k] * w; a3 += sx[384 + k] * w;
    }
    float bj = b1[j];
    if (r0 + 0 < n_r) g_hid[(r0 + 0) * 256 + j] = a0 + bj;
    if (r0 + 1 < n_r) g_hid[(r0 + 1) * 256 + j] = a1 + bj;
    if (r0 + 2 < n_r) g_hid[(r0 + 2) * 256 + j] = a2 + bj;
    if (r0 + 3 < n_r) g_hid[(r0 + 3) * 256 + j] = a3 + bj;
}

// ---------------- msg = x_r + hid @ W2 + b2 ----------------
__global__ void k_msg(const float* __restrict__ xr, const float* __restrict__ W2,
                      const float* __restrict__ b2, int n_r) {
    __shared__ float sh[1024];  // 4 hid rows x 256
    int r0 = blockIdx.x * 4;
    for (int i = threadIdx.x; i < 1024; i += 128) {
        int rr = i >> 8, k = i & 255, r = r0 + rr;
        sh[i] = (r < n_r) ? g_hid[r * 256 + k] : 0.f;
    }
    __syncthreads();
    int j = threadIdx.x;
    float a0 = 0, a1 = 0, a2 = 0, a3 = 0;
#pragma unroll 4
    for (int k = 0; k < 256; k++) {
        float w = W2[k * 128 + j];
        a0 += sh[k] * w; a1 += sh[256 + k] * w; a2 += sh[512 + k] * w; a3 += sh[768 + k] * w;
    }
    float bj = b2[j];
    if (r0 + 0 < n_r) g_msg[(r0 + 0) * 128 + j] = a0 + bj + xr[(r0 + 0) * 128 + j];
    if (r0 + 1 < n_r) g_msg[(r0 + 1) * 128 + j] = a1 + bj + xr[(r0 + 1) * 128 + j];
    if (r0 + 2 < n_r) g_msg[(r0 + 2) * 128 + j] = a2 + bj + xr[(r0 + 2) * 128 + j];
    if (r0 + 3 < n_r) g_msg[(r0 + 3) * 128 + j] = a3 + bj + xr[(r0 + 3) * 128 + j];
}

// ---------------- P_h = msg @ W_r[:128,:], P_t = msg @ W_r[128:,:], chunked layout ----------------
__global__ void k_P(const float* __restrict__ Wr, int n_r) {
    __shared__ float sm[512];  // 4 msg rows x 128
    int r0 = blockIdx.x * 4;
    for (int i = threadIdx.x; i < 512; i += 256) {
        int rr = i >> 7, k = i & 127, r = r0 + rr;
        sm[i] = (r < n_r) ? g_msg[r * 128 + k] : 0.f;
    }
    __syncthreads();
    int j = threadIdx.x;
    float h0 = 0, h1 = 0, h2 = 0, h3 = 0, t0 = 0, t1 = 0, t2 = 0, t3 = 0;
#pragma unroll 2
    for (int k = 0; k < 128; k++) {
        float wh = Wr[k * 256 + j];
        float wt = Wr[(128 + k) * 256 + j];
        float m0 = sm[k], m1 = sm[128 + k], m2 = sm[256 + k], m3 = sm[384 + k];
        h0 += m0 * wh; h1 += m1 * wh; h2 += m2 * wh; h3 += m3 * wh;
        t0 += m0 * wt; t1 += m1 * wt; t2 += m2 * wt; t3 += m3 * wt;
    }
    int c = j >> 5, l = j & 31;
    float hv[4] = {h0, h1, h2, h3}, tv[4] = {t0, t1, t2, t3};
#pragma unroll
    for (int i = 0; i < 4; i++) {
        int r = r0 + i;
        if (r < n_r) {
            g_P[(c * n_r + r) * 32 + l]       = hv[i];
            g_P[((8 + c) * n_r + r) * 32 + l] = tv[i];
        }
    }
}

// ---------------- histogram ----------------
__global__ void k_hist(const int* __restrict__ h, const int* __restrict__ t, int E) {
    int e = blockIdx.x * blockDim.x + threadIdx.x;
    if (e < E) {
        atomicAdd(&g_cnt_h[h[e]], 1);
        atomicAdd(&g_cnt_t[t[e]], 1);
    }
}

// ---------------- scan (3 phases), grid.y selects h/t ----------------
__global__ void k_scan1(int n_e) {
    __shared__ int s[1024];
    int y = blockIdx.y;
    const int* cnt = y ? g_cnt_t : g_cnt_h;
    int* st = y ? g_starts_t : g_starts_h;
    int i = blockIdx.x * 1024 + threadIdx.x;
    int v = (i < n_e) ? cnt[i] : 0;
    s[threadIdx.x] = v;
    __syncthreads();
    for (int o = 1; o < 1024; o <<= 1) {
        int tv = (threadIdx.x >= (unsigned)o) ? s[threadIdx.x - o] : 0;
        __syncthreads();
        s[threadIdx.x] += tv;
        __syncthreads();
    }
    if (i < n_e) st[i] = s[threadIdx.x];  // inclusive partial
    if (threadIdx.x == 1023) g_bsum[y][blockIdx.x] = s[1023];
}

__global__ void k_scan2(int nb) {
    if (threadIdx.x != 0) return;
    int y = blockIdx.x;
    int acc = 0;
    for (int b = 0; b < nb; b++) { int t = g_bsum[y][b]; g_bsum[y][b] = acc; acc += t; }
    g_bsum[y][nb] = acc;
}

__global__ void k_scan3(int n_e, int nb) {
    int y = blockIdx.y;
    const int* cnt = y ? g_cnt_t : g_cnt_h;
    int* st = y ? g_starts_t : g_starts_h;
    int* cur = y ? g_cur_t : g_cur_h;
    int i = blockIdx.x * 1024 + threadIdx.x;
    if (i < n_e) {
        int ex = st[i] - cnt[i] + g_bsum[y][blockIdx.x];  // exclusive
        st[i] = ex;
        cur[i] = ex;
    }
    if (i == 0) st[n_e] = g_bsum[y][nb];
}

// ---------------- place edges into sorted order, computing z = exp(leaky(...)) inline ----------------
// NOTE: max-shift skipped deliberately — alpha is shift-invariant and logits are O(5),
// so exp cannot overflow; the +1e-16 denominator perturbation is ~1e-14 relative.
__global__ void k_place(const int* __restrict__ h, const int* __restrict__ t,
                        const int* __restrict__ rel, int E) {
    int e = blockIdx.x * blockDim.x + threadIdx.x;
    if (e >= E) return;
    int hn = h[e], tn = t[e], r = rel[e];
    float sr = g_sr[r];
    float lh = g_sh[hn] + sr; lh = (lh > 0.f) ? lh : 0.01f * lh;
    float lt = g_st[tn] + sr; lt = (lt > 0.f) ? lt : 0.01f * lt;
    float zh = __expf(lh), zt = __expf(lt);
    float ro = __int_as_float(r * 32);  // word offset of rel row in a 32-feat smem chunk
    int ph = atomicAdd(&g_cur_h[hn], 1);
    g_pack_h[ph] = make_float2(zh, ro);
    int pt = atomicAdd(&g_cur_t[tn], 1);
    g_pack_t[pt] = make_float2(zt, ro);
}

// ---------------- per-node softmax denominators; normalize z -> alpha in place ----------------
__global__ void k_denom(int n_e) {
    int n = blockIdx.x * blockDim.x + threadIdx.x;
    if (n >= n_e) return;
    {
        int s0 = g_starts_h[n], s1 = g_starts_h[n + 1];
        float S = 0.f;
        for (int i = s0; i < s1; i++) S += g_pack_h[i].x;
        float inv = 1.f / (S + 1e-16f);
        for (int i = s0; i < s1; i++) g_pack_h[i].x *= inv;
    }
    {
        int s0 = g_starts_t[n], s1 = g_starts_t[n + 1];
        float S = 0.f;
        for (int i = s0; i < s1; i++) S += g_pack_t[i].x;
        float inv = 1.f / (S + 1e-16f);
        for (int i = s0; i < s1; i++) g_pack_t[i].x *= inv;
    }
}

// ---------------- main SpMM: out[n, 32c..32c+32) = b + sum_h alpha*P_h[rel] + sum_t alpha*P_t[rel]
// grid = (8 feature chunks, node slices); warp per node, lane per feature.
// Phase A (h side) writes out once (covers the 0xAA poison), phase B (t side) RMWs — same warp,
// same lane, disjoint (slice x chunk) partitions => no races.
__global__ __launch_bounds__(1024, 1) void k_main(const float* __restrict__ br,
                                                  float* __restrict__ out,
                                                  int n_e, int n_r) {
    extern __shared__ float sP[];  // n_r * 32 floats = 128 KB
    int pass = blockIdx.x;         // feature chunk 0..7
    int nslices = gridDim.y;
    int ns_per = (n_e + nslices - 1) / nslices;
    int n0 = blockIdx.y * ns_per;
    int n1 = min(n0 + ns_per, n_e);
    int lane = threadIdx.x & 31;
    int warp = threadIdx.x >> 5;
    int nwarp = blockDim.x >> 5;
    float bv = br[pass * 32 + lane];
    int chunk_words = n_r * 32;

    // ---- phase A: h side ----
    const float* src = g_P + (size_t)pass * chunk_words;
    for (int i = threadIdx.x; i < chunk_words; i += blockDim.x) sP[i] = src[i];
    __syncthreads();
    for (int n = n0 + warp; n < n1; n += nwarp) {
        int s0 = g_starts_h[n], s1 = g_starts_h[n + 1];
        float acc = 0.f;
        for (int i = s0; i < s1; i++) {
            float2 p = g_pack_h[i];
            acc += p.x * sP[__float_as_int(p.y) + lane];
        }
        out[(size_t)n * 256 + pass * 32 + lane] = bv + acc;
    }
    __syncthreads();

    // ---- phase B: t side ----
    src = g_P + (size_t)(8 + pass) * chunk_words;
    for (int i = threadIdx.x; i < chunk_words; i += blockDim.x) sP[i] = src[i];
    __syncthreads();
    for (int n = n0 + warp; n < n1; n += nwarp) {
        int s0 = g_starts_t[n], s1 = g_starts_t[n + 1];
        float acc = 0.f;
        for (int i = s0; i < s1; i++) {
            float2 p = g_pack_t[i];
            acc += p.x * sP[__float_as_int(p.y) + lane];
        }
        size_t o = (size_t)n * 256 + pass * 32 + lane;
        out[o] += acc;
    }
}

// ---------------- launch ----------------
extern "C" void kernel_launch(void* const* d_in, const int* in_sizes, int n_in,
                              void* d_out, int out_size) {
    const float* xe  = (const float*)d_in[0];
    const float* xr  = (const float*)d_in[1];
    const int*   ei  = (const int*)d_in[2];
    const int*   rel = (const int*)d_in[3];
    // d_in[4] = rel_all (unused by the reference)
    const float* wah = (const float*)d_in[5];
    const float* wat = (const float*)d_in[6];
    const float* war = (const float*)d_in[7];
    const float* W1  = (const float*)d_in[8];
    const float* b1  = (const float*)d_in[9];
    const float* W2  = (const float*)d_in[10];
    const float* b2  = (const float*)d_in[11];
    const float* Wr  = (const float*)d_in[12];
    const float* br  = (const float*)d_in[13];
    float* out = (float*)d_out;

    int n_e = in_sizes[0] / 128;
    int n_r = in_sizes[1] / 128;
    int E   = in_sizes[3];
    const int* h = ei;
    const int* t = ei + E;
    int nb = (n_e + 1023) / 1024;

    cudaFuncSetAttribute(k_main, cudaFuncAttributeMaxDynamicSharedMemorySize, 131072);

    k_zero<<<(n_e + 255) / 256, 256>>>(n_e);
    k_node_scores<<<(n_e * 32 + 255) / 256, 256>>>((const float4*)xe, (const float4*)wah,
                                                   (const float4*)wat, n_e);
    k_rel_scores<<<(n_r * 32 + 255) / 256, 256>>>((const float4*)xr, (const float4*)war, n_r);
    k_hid<<<(n_r + 3) / 4, 256>>>(xr, W1, b1, n_r);
    k_msg<<<(n_r + 3) / 4, 128>>>(xr, W2, b2, n_r);
    k_P<<<(n_r + 3) / 4, 256>>>(Wr, n_r);
    k_hist<<<(E + 255) / 256, 256>>>(h, t, E);
    k_scan1<<<dim3(nb, 2), 1024>>>(n_e);
    k_scan2<<<2, 32>>>(nb);
    k_scan3<<<dim3(nb, 2), 1024>>>(n_e, nb);
    k_place<<<(E + 255) / 256, 256>>>(h, t, rel, E);
    k_denom<<<(n_e + 127) / 128, 128>>>(n_e);

    dim3 g(8, 18);  // 144 blocks = one wave on 148 SMs, 1 block/SM (128 KB smem)
    k_main<<<g, 1024, (size_t)n_r * 32 * sizeof(float)>>>(br, out, n_e, n_r);
}

// round 2
// speedup vs baseline: 1.1996x; 1.1996x over previous
#include <cuda_runtime.h>
#include <math.h>

#define MAX_NE 100000
#define MAX_NR 1000
#define MAX_E  1000000

// ---------------- scratch ----------------
__device__ float  g_sh[MAX_NE];
__device__ float  g_st[MAX_NE];
__device__ float  g_sr[MAX_NR];
__device__ float  g_W12[128 * 128];        // W1 @ W2
__device__ float  g_c0[128];               // b1 @ W2 + b2
__device__ float  g_Mh[128 * 256];         // (I + W1W2) @ Wr_top
__device__ float  g_Mt[128 * 256];         // (I + W1W2) @ Wr_bot
__device__ float  g_ch[256];               // c0 @ Wr_top
__device__ float  g_ct[256];               // c0 @ Wr_bot
__device__ float  g_P[16 * MAX_NR * 32];   // [chunk(16)][rel][32]; h: 0..7, t: 8..15
__device__ int    g_cnt_h[MAX_NE];
__device__ int    g_cnt_t[MAX_NE];
__device__ int    g_starts_h[MAX_NE + 1];
__device__ int    g_starts_t[MAX_NE + 1];
__device__ int    g_cur_h[MAX_NE];
__device__ int    g_cur_t[MAX_NE];
__device__ float  g_inv_h[MAX_NE];
__device__ float  g_inv_t[MAX_NE];
__device__ float2 g_pack_h[MAX_E];         // {z, rel*32 as float bits}, sorted by h
__device__ float2 g_pack_t[MAX_E];
__device__ int    g_bsum[2][160];

// ---------------- init ----------------
__global__ void k_zero(int n_e) {
    int i = blockIdx.x * blockDim.x + threadIdx.x;
    if (i < n_e) { g_cnt_h[i] = 0; g_cnt_t[i] = 0; }
}

// ---------------- per-node attention scores ----------------
__global__ void k_node_scores(const float4* __restrict__ xe,
                              const float4* __restrict__ wah4,
                              const float4* __restrict__ wat4, int n_e) {
    int gw = (blockIdx.x * blockDim.x + threadIdx.x) >> 5;
    int lane = threadIdx.x & 31;
    if (gw >= n_e) return;
    float4 v = xe[(size_t)gw * 32 + lane];
    float4 a = wah4[lane];
    float4 b = wat4[lane];
    float da = v.x * a.x + v.y * a.y + v.z * a.z + v.w * a.w;
    float db = v.x * b.x + v.y * b.y + v.z * b.z + v.w * b.w;
#pragma unroll
    for (int o = 16; o > 0; o >>= 1) {
        da += __shfl_xor_sync(0xffffffffu, da, o);
        db += __shfl_xor_sync(0xffffffffu, db, o);
    }
    if (lane == 0) { g_sh[gw] = da; g_st[gw] = db; }
}

__global__ void k_rel_scores(const float4* __restrict__ xr,
                             const float4* __restrict__ war4, int n_r) {
    int gw = (blockIdx.x * blockDim.x + threadIdx.x) >> 5;
    int lane = threadIdx.x & 31;
    if (gw >= n_r) return;
    float4 v = xr[gw * 32 + lane];
    float4 a = war4[lane];
    float d = v.x * a.x + v.y * a.y + v.z * a.z + v.w * a.w;
#pragma unroll
    for (int o = 16; o > 0; o >>= 1) d += __shfl_xor_sync(0xffffffffu, d, o);
    if (lane == 0) g_sr[gw] = d;
}

// ---------------- weight prep: W12 = W1@W2, c0 = b1@W2 + b2 ----------------
__global__ void k_w12(const float* __restrict__ W1, const float* __restrict__ b1,
                      const float* __restrict__ W2, const float* __restrict__ b2) {
    __shared__ float s[256];
    int i = blockIdx.x;  // 0..128 (128 = bias row)
    const float* row = (i < 128) ? (W1 + i * 256) : b1;
    for (int k = threadIdx.x; k < 256; k += 128) s[k] = row[k];
    __syncthreads();
    int j = threadIdx.x;
    float acc = 0.f;
#pragma unroll 8
    for (int k = 0; k < 256; k++) acc += s[k] * W2[k * 128 + j];
    if (i < 128) g_W12[i * 128 + j] = acc;
    else         g_c0[j] = acc + b2[j];
}

// ---------------- Meff = (I + W12) @ Wr halves; c vectors ----------------
__global__ void k_meff(const float* __restrict__ Wr) {
    __shared__ float s[128];
    int i = blockIdx.x;  // 0..128 (128 = c0 row)
    const float* row = (i < 128) ? (g_W12 + i * 128) : g_c0;
    if (threadIdx.x < 128) s[threadIdx.x] = row[threadIdx.x];
    __syncthreads();
    int j = threadIdx.x;  // 0..255
    float mh = 0.f, mt = 0.f;
#pragma unroll 4
    for (int k = 0; k < 128; k++) {
        float v = s[k];
        mh += v * Wr[k * 256 + j];
        mt += v * Wr[(128 + k) * 256 + j];
    }
    if (i < 128) {
        g_Mh[i * 256 + j] = mh + Wr[i * 256 + j];
        g_Mt[i * 256 + j] = mt + Wr[(128 + i) * 256 + j];
    } else {
        g_ch[j] = mh;
        g_ct[j] = mt;
    }
}

// ---------------- P tables: P_h[r] = x_r[r]@Mh + ch; P_t likewise; chunked layout ----------------
__global__ void k_ptab(const float* __restrict__ xr, int n_r) {
    __shared__ float sx[8 * 128];
    int r0 = blockIdx.x * 8;
    for (int i = threadIdx.x; i < 1024; i += 256) {
        int rr = i >> 7, k = i & 127, r = r0 + rr;
        sx[i] = (r < n_r) ? xr[r * 128 + k] : 0.f;
    }
    __syncthreads();
    int j = threadIdx.x;
    float ah[8], at[8];
    float chj = g_ch[j], ctj = g_ct[j];
#pragma unroll
    for (int u = 0; u < 8; u++) { ah[u] = chj; at[u] = ctj; }
#pragma unroll 2
    for (int k = 0; k < 128; k++) {
        float wh = g_Mh[k * 256 + j];
        float wt = g_Mt[k * 256 + j];
#pragma unroll
        for (int u = 0; u < 8; u++) {
            float x = sx[u * 128 + k];
            ah[u] += x * wh;
            at[u] += x * wt;
        }
    }
    int c = j >> 5, l = j & 31;
#pragma unroll
    for (int u = 0; u < 8; u++) {
        int r = r0 + u;
        if (r < n_r) {
            g_P[(c * n_r + r) * 32 + l]       = ah[u];
            g_P[((8 + c) * n_r + r) * 32 + l] = at[u];
        }
    }
}

// ---------------- histogram ----------------
__global__ void k_hist(const int* __restrict__ h, const int* __restrict__ t, int E) {
    int e = blockIdx.x * blockDim.x + threadIdx.x;
    if (e < E) {
        atomicAdd(&g_cnt_h[h[e]], 1);
        atomicAdd(&g_cnt_t[t[e]], 1);
    }
}

// ---------------- scan ----------------
__global__ void k_scan1(int n_e) {
    __shared__ int s[1024];
    int y = blockIdx.y;
    const int* cnt = y ? g_cnt_t : g_cnt_h;
    int* st = y ? g_starts_t : g_starts_h;
    int i = blockIdx.x * 1024 + threadIdx.x;
    int v = (i < n_e) ? cnt[i] : 0;
    s[threadIdx.x] = v;
    __syncthreads();
    for (int o = 1; o < 1024; o <<= 1) {
        int tv = (threadIdx.x >= (unsigned)o) ? s[threadIdx.x - o] : 0;
        __syncthreads();
        s[threadIdx.x] += tv;
        __syncthreads();
    }
    if (i < n_e) st[i] = s[threadIdx.x];
    if (threadIdx.x == 1023) g_bsum[y][blockIdx.x] = s[1023];
}

__global__ void k_scan2(int nb) {
    if (threadIdx.x != 0) return;
    int y = blockIdx.x;
    int acc = 0;
    for (int b = 0; b < nb; b++) { int t = g_bsum[y][b]; g_bsum[y][b] = acc; acc += t; }
    g_bsum[y][nb] = acc;
}

__global__ void k_scan3(int n_e, int nb) {
    int y = blockIdx.y;
    const int* cnt = y ? g_cnt_t : g_cnt_h;
    int* st = y ? g_starts_t : g_starts_h;
    int* cur = y ? g_cur_t : g_cur_h;
    int i = blockIdx.x * 1024 + threadIdx.x;
    if (i < n_e) {
        int ex = st[i] - cnt[i] + g_bsum[y][blockIdx.x];
        st[i] = ex;
        cur[i] = ex;
    }
    if (i == 0) st[n_e] = g_bsum[y][nb];
}

// ---------------- place edges (z computed inline; max-shift skipped: logits O(5)) ----------------
__global__ void k_place(const int* __restrict__ h, const int* __restrict__ t,
                        const int* __restrict__ rel, int E) {
    int e = blockIdx.x * blockDim.x + threadIdx.x;
    if (e >= E) return;
    int hn = h[e], tn = t[e], r = rel[e];
    float sr = g_sr[r];
    float lh = g_sh[hn] + sr; lh = (lh > 0.f) ? lh : 0.01f * lh;
    float lt = g_st[tn] + sr; lt = (lt > 0.f) ? lt : 0.01f * lt;
    float zh = __expf(lh), zt = __expf(lt);
    float ro = __int_as_float(r * 32);
    int ph = atomicAdd(&g_cur_h[hn], 1);
    g_pack_h[ph] = make_float2(zh, ro);
    int pt = atomicAdd(&g_cur_t[tn], 1);
    g_pack_t[pt] = make_float2(zt, ro);
}

// ---------------- per-node inverse softmax denominators (no normalize pass) ----------------
__global__ void k_denom(int n_e) {
    int n = blockIdx.x * blockDim.x + threadIdx.x;
    if (n >= n_e) return;
    {
        int s0 = g_starts_h[n], s1 = g_starts_h[n + 1];
        float S = 0.f;
        for (int i = s0; i < s1; i += 4) {
#pragma unroll
            for (int u = 0; u < 4; u++) {
                int j = i + u;
                float v = (j < s1) ? g_pack_h[j].x : 0.f;
                S += v;
            }
        }
        g_inv_h[n] = 1.f / (S + 1e-16f);
    }
    {
        int s0 = g_starts_t[n], s1 = g_starts_t[n + 1];
        float S = 0.f;
        for (int i = s0; i < s1; i += 4) {
#pragma unroll
            for (int u = 0; u < 4; u++) {
                int j = i + u;
                float v = (j < s1) ? g_pack_t[j].x : 0.f;
                S += v;
            }
        }
        g_inv_t[n] = 1.f / (S + 1e-16f);
    }
}

// ---------------- main SpMM with 8-wide predicated unroll + node prefetch ----------------
__global__ __launch_bounds__(1024, 1) void k_main(const float* __restrict__ br,
                                                  float* __restrict__ out,
                                                  int n_e, int n_r) {
    extern __shared__ float sP[];  // n_r * 32 floats
    int pass = blockIdx.x;
    int nslices = gridDim.y;
    int ns_per = (n_e + nslices - 1) / nslices;
    int n0 = blockIdx.y * ns_per;
    int n1 = min(n0 + ns_per, n_e);
    int lane = threadIdx.x & 31;
    int warp = threadIdx.x >> 5;
    int nwarp = blockDim.x >> 5;
    float bv = br[pass * 32 + lane];
    const float* sPl = sP + lane;
    int chunk_words = n_r * 32;

    // ---- phase A: h side (writes out, covering poison) ----
    {
        const float4* s4 = (const float4*)(g_P + (size_t)pass * chunk_words);
        float4* d4 = (float4*)sP;
        for (int i = threadIdx.x; i < (chunk_words >> 2); i += blockDim.x) d4[i] = s4[i];
    }
    __syncthreads();
    {
        const float2* __restrict__ pk = g_pack_h;
        int n = n0 + warp;
        if (n < n1) {
            int s0 = g_starts_h[n];
            int s1 = g_starts_h[n + 1];
            float inv = g_inv_h[n];
            while (true) {
                int nn = n + nwarp;
                int t0 = 0, t1 = 0; float tinv = 0.f;
                if (nn < n1) { t0 = g_starts_h[nn]; t1 = g_starts_h[nn + 1]; tinv = g_inv_h[nn]; }
                float acc = 0.f;
                for (int i = s0; i < s1; i += 8) {
#pragma unroll
                    for (int u = 0; u < 8; u++) {
                        int j = i + u;
                        float2 p = (j < s1) ? pk[j] : make_float2(0.f, 0.f);
                        acc += p.x * sPl[__float_as_int(p.y)];
                    }
                }
                out[(size_t)n * 256 + pass * 32 + lane] = bv + acc * inv;
                if (nn >= n1) break;
                n = nn; s0 = t0; s1 = t1; inv = tinv;
            }
        }
    }
    __syncthreads();

    // ---- phase B: t side (RMW) ----
    {
        const float4* s4 = (const float4*)(g_P + (size_t)(8 + pass) * chunk_words);
        float4* d4 = (float4*)sP;
        for (int i = threadIdx.x; i < (chunk_words >> 2); i += blockDim.x) d4[i] = s4[i];
    }
    __syncthreads();
    {
        const float2* __restrict__ pk = g_pack_t;
        int n = n0 + warp;
        if (n < n1) {
            int s0 = g_starts_t[n];
            int s1 = g_starts_t[n + 1];
            float inv = g_inv_t[n];
            while (true) {
                int nn = n + nwarp;
                int t0 = 0, t1 = 0; float tinv = 0.f;
                if (nn < n1) { t0 = g_starts_t[nn]; t1 = g_starts_t[nn + 1]; tinv = g_inv_t[nn]; }
                float acc = 0.f;
                for (int i = s0; i < s1; i += 8) {
#pragma unroll
                    for (int u = 0; u < 8; u++) {
                        int j = i + u;
                        float2 p = (j < s1) ? pk[j] : make_float2(0.f, 0.f);
                        acc += p.x * sPl[__float_as_int(p.y)];
                    }
                }
                size_t o = (size_t)n * 256 + pass * 32 + lane;
                out[o] += acc * inv;
                if (nn >= n1) break;
                n = nn; s0 = t0; s1 = t1; inv = tinv;
            }
        }
    }
}

// ---------------- launch ----------------
extern "C" void kernel_launch(void* const* d_in, const int* in_sizes, int n_in,
                              void* d_out, int out_size) {
    const float* xe  = (const float*)d_in[0];
    const float* xr  = (const float*)d_in[1];
    const int*   ei  = (const int*)d_in[2];
    const int*   rel = (const int*)d_in[3];
    const float* wah = (const float*)d_in[5];
    const float* wat = (const float*)d_in[6];
    const float* war = (const float*)d_in[7];
    const float* W1  = (const float*)d_in[8];
    const float* b1  = (const float*)d_in[9];
    const float* W2  = (const float*)d_in[10];
    const float* b2  = (const float*)d_in[11];
    const float* Wr  = (const float*)d_in[12];
    const float* br  = (const float*)d_in[13];
    float* out = (float*)d_out;

    int n_e = in_sizes[0] / 128;
    int n_r = in_sizes[1] / 128;
    int E   = in_sizes[3];
    const int* h = ei;
    const int* t = ei + E;
    int nb = (n_e + 1023) / 1024;

    cudaFuncSetAttribute(k_main, cudaFuncAttributeMaxDynamicSharedMemorySize, 131072);

    k_zero<<<(n_e + 255) / 256, 256>>>(n_e);
    k_node_scores<<<(n_e * 32 + 255) / 256, 256>>>((const float4*)xe, (const float4*)wah,
                                                   (const float4*)wat, n_e);
    k_rel_scores<<<(n_r * 32 + 255) / 256, 256>>>((const float4*)xr, (const float4*)war, n_r);
    k_w12<<<129, 128>>>(W1, b1, W2, b2);
    k_meff<<<129, 256>>>(Wr);
    k_ptab<<<(n_r + 7) / 8, 256>>>(xr, n_r);
    k_hist<<<(E + 255) / 256, 256>>>(h, t, E);
    k_scan1<<<dim3(nb, 2), 1024>>>(n_e);
    k_scan2<<<2, 32>>>(nb);
    k_scan3<<<dim3(nb, 2), 1024>>>(n_e, nb);
    k_place<<<(E + 255) / 256, 256>>>(h, t, rel, E);
    k_denom<<<(n_e + 127) / 128, 128>>>(n_e);

    dim3 g(8, 18);
    k_main<<<g, 1024, (size_t)n_r * 32 * sizeof(float)>>>(br, out, n_e, n_r);
}